// round 1
// baseline (speedup 1.0000x reference)
#include <cuda_runtime.h>
#include <math.h>

// ---------------- problem constants ----------------
#define NMAX 50000
#define EMAX 800000
#define CH   128     // hidden width (layers 0,1)
#define LOUT 64      // final width

// ---------------- device scratch (static; no allocations allowed) ----------------
__device__ float g_deg[NMAX];
__device__ float g_dis[NMAX];
__device__ float g_selfnorm[NMAX];
__device__ int   g_count[NMAX];
__device__ int   g_rowstart[NMAX + 1];
__device__ int   g_cursor[NMAX];
__device__ int   g_csr_src[EMAX];
__device__ float g_csr_nm[EMAX];
__device__ float g_tmp[(size_t)NMAX * CH];   // GEMM output
__device__ float g_agg[(size_t)NMAX * CH];   // aggregation output
__device__ float g_h[(size_t)NMAX * CH];     // layer activation
__device__ float g_bnsum[CH];
__device__ float g_bnsq[CH];
__device__ int   g_is64;

// ---------------- helpers ----------------
__device__ __forceinline__ int fetch_idx(const void* p, long long i, int is64) {
    if (is64) return (int)((const long long*)p)[i];
    return ((const int*)p)[i];
}

// Detect whether edge_index is int64 (odd 32-bit words all zero) or int32.
__global__ void k_detect(const void* ei) {
    const int* w = (const int*)ei;
    int z = 1;
    #pragma unroll
    for (int i = 1; i <= 9; i += 2) if (w[i] != 0) z = 0;
    g_is64 = z;
}

__global__ void k_init(int N) {
    int i = blockIdx.x * blockDim.x + threadIdx.x;
    if (i < N) { g_deg[i] = 1.0f; g_count[i] = 0; }   // self-loop weight 1 pre-added
}

__global__ void k_deg(const void* ei, const float* __restrict__ ew, int E) {
    int e = blockIdx.x * blockDim.x + threadIdx.x;
    if (e >= E) return;
    int is64 = g_is64;
    int d = fetch_idx(ei, (long long)E + e, is64);
    atomicAdd(&g_deg[d], ew[e]);
    atomicAdd(&g_count[d], 1);
}

__global__ void k_dis(int N) {
    int i = blockIdx.x * blockDim.x + threadIdx.x;
    if (i >= N) return;
    float d = rsqrtf(g_deg[i]);   // deg >= 1 always (self loop)
    g_dis[i] = d;
    g_selfnorm[i] = d * d;        // dis[i]*1*dis[i]
}

// Single-block exclusive scan of g_count -> g_rowstart (+cursor copy).
__global__ void k_scan(int N) {
    __shared__ int ssum[1024];
    int t = threadIdx.x;
    int chunk = (N + 1023) / 1024;
    int lo = t * chunk;
    int hi = min(lo + chunk, N);
    int s = 0;
    for (int i = lo; i < hi; i++) s += g_count[i];
    ssum[t] = s;
    __syncthreads();
    for (int off = 1; off < 1024; off <<= 1) {
        int v = (t >= off) ? ssum[t - off] : 0;
        __syncthreads();
        ssum[t] += v;
        __syncthreads();
    }
    int base = (t == 0) ? 0 : ssum[t - 1];
    for (int i = lo; i < hi; i++) {
        g_rowstart[i] = base;
        g_cursor[i]   = base;
        base += g_count[i];
    }
    if (t == 1023) g_rowstart[N] = ssum[1023];
}

__global__ void k_fill(const void* ei, const float* __restrict__ ew, int E) {
    int e = blockIdx.x * blockDim.x + threadIdx.x;
    if (e >= E) return;
    int is64 = g_is64;
    int s = fetch_idx(ei, e, is64);
    int d = fetch_idx(ei, (long long)E + e, is64);
    float nm = g_dis[s] * ew[e] * g_dis[d];
    int pos = atomicAdd(&g_cursor[d], 1);
    g_csr_src[pos] = s;
    g_csr_nm[pos]  = nm;
}

// ---------------- SGEMM: g_tmp = A[N,128] @ W[128,COUT] ----------------
template<int COUT>
__global__ __launch_bounds__(256) void k_gemm(const float* __restrict__ A,
                                              const float* __restrict__ W, int N) {
    constexpr int BM = 128, BK = 16, TN = COUT / 16;
    __shared__ float As[BK][BM + 4];
    __shared__ float Bs[BK][COUT];
    int tid = threadIdx.x;
    int brow = blockIdx.x * BM;
    int ty = tid >> 4, tx = tid & 15;
    float acc[8][TN];
    #pragma unroll
    for (int i = 0; i < 8; i++)
        #pragma unroll
        for (int j = 0; j < TN; j++) acc[i][j] = 0.f;

    for (int k0 = 0; k0 < 128; k0 += BK) {
        // A tile: 128 rows x 16 k, transposed into As[k][row]
        #pragma unroll
        for (int q = 0; q < 2; q++) {
            int f = tid * 2 + q;          // 0..511 float4s
            int row = f >> 2, kq = f & 3;
            int gr = brow + row;
            float4 v = make_float4(0.f, 0.f, 0.f, 0.f);
            if (gr < N) v = *(const float4*)&A[(size_t)gr * 128 + k0 + kq * 4];
            As[kq * 4 + 0][row] = v.x;
            As[kq * 4 + 1][row] = v.y;
            As[kq * 4 + 2][row] = v.z;
            As[kq * 4 + 3][row] = v.w;
        }
        // B tile: 16 x COUT, row-major
        constexpr int BF4 = BK * COUT / 4;
        #pragma unroll
        for (int f = tid; f < BF4; f += 256) {
            int row = f / (COUT / 4), cq = f % (COUT / 4);
            *(float4*)&Bs[row][cq * 4] = *(const float4*)&W[(size_t)(k0 + row) * COUT + cq * 4];
        }
        __syncthreads();
        #pragma unroll
        for (int kk = 0; kk < BK; kk++) {
            float a[8], b[TN];
            #pragma unroll
            for (int i = 0; i < 2; i++) {
                float4 av = *(const float4*)&As[kk][ty * 8 + i * 4];
                a[i * 4 + 0] = av.x; a[i * 4 + 1] = av.y;
                a[i * 4 + 2] = av.z; a[i * 4 + 3] = av.w;
            }
            #pragma unroll
            for (int j = 0; j < TN / 4; j++) {
                float4 bv = *(const float4*)&Bs[kk][tx * TN + j * 4];
                b[j * 4 + 0] = bv.x; b[j * 4 + 1] = bv.y;
                b[j * 4 + 2] = bv.z; b[j * 4 + 3] = bv.w;
            }
            #pragma unroll
            for (int i = 0; i < 8; i++)
                #pragma unroll
                for (int j = 0; j < TN; j++)
                    acc[i][j] = fmaf(a[i], b[j], acc[i][j]);
        }
        __syncthreads();
    }
    #pragma unroll
    for (int i = 0; i < 8; i++) {
        int r = brow + ty * 8 + i;
        if (r < N) {
            #pragma unroll
            for (int j = 0; j < TN / 4; j++)
                *(float4*)&g_tmp[(size_t)r * COUT + tx * TN + j * 4] =
                    make_float4(acc[i][j * 4], acc[i][j * 4 + 1], acc[i][j * 4 + 2], acc[i][j * 4 + 3]);
        }
    }
}

// ---------------- aggregation: warp per node, CSR gather ----------------
template<int COUT>
__global__ void k_agg(const float* __restrict__ bias, int N) {
    int gw   = (blockIdx.x * blockDim.x + threadIdx.x) >> 5;
    int lane = threadIdx.x & 31;
    if (gw >= N) return;
    constexpr int V = COUT / 32;
    const float* __restrict__ tmp = g_tmp;
    float sn = g_selfnorm[gw];
    float acc[V];
    if constexpr (V == 4) {
        float4 t  = *(const float4*)&tmp[(size_t)gw * COUT + lane * 4];
        float4 b4 = *(const float4*)&bias[lane * 4];
        acc[0] = b4.x + sn * t.x; acc[1] = b4.y + sn * t.y;
        acc[2] = b4.z + sn * t.z; acc[3] = b4.w + sn * t.w;
    } else {
        float2 t  = *(const float2*)&tmp[(size_t)gw * COUT + lane * 2];
        float2 b2 = *(const float2*)&bias[lane * 2];
        acc[0] = b2.x + sn * t.x; acc[1] = b2.y + sn * t.y;
    }
    int r0 = g_rowstart[gw], r1 = g_rowstart[gw + 1];
    for (int e = r0; e < r1; e++) {
        int   s  = g_csr_src[e];
        float nm = g_csr_nm[e];
        if constexpr (V == 4) {
            float4 v = *(const float4*)&tmp[(size_t)s * COUT + lane * 4];
            acc[0] = fmaf(nm, v.x, acc[0]); acc[1] = fmaf(nm, v.y, acc[1]);
            acc[2] = fmaf(nm, v.z, acc[2]); acc[3] = fmaf(nm, v.w, acc[3]);
        } else {
            float2 v = *(const float2*)&tmp[(size_t)s * COUT + lane * 2];
            acc[0] = fmaf(nm, v.x, acc[0]); acc[1] = fmaf(nm, v.y, acc[1]);
        }
    }
    if constexpr (V == 4) {
        *(float4*)&g_agg[(size_t)gw * COUT + lane * 4] = make_float4(acc[0], acc[1], acc[2], acc[3]);
    } else {
        *(float2*)&g_agg[(size_t)gw * COUT + lane * 2] = make_float2(acc[0], acc[1]);
    }
}

// ---------------- BatchNorm ----------------
__global__ void k_zerobn() {
    g_bnsum[threadIdx.x] = 0.f;
    g_bnsq[threadIdx.x]  = 0.f;
}

template<int COUT>
__global__ void k_bnreduce(int N) {
    int c = threadIdx.x;                 // blockDim = COUT
    int nb = gridDim.x;
    int chunk = (N + nb - 1) / nb;
    int lo = blockIdx.x * chunk;
    int hi = min(lo + chunk, N);
    float s = 0.f, q = 0.f;
    for (int r = lo; r < hi; r++) {
        float v = g_agg[(size_t)r * COUT + c];
        s += v;
        q = fmaf(v, v, q);
    }
    atomicAdd(&g_bnsum[c], s);
    atomicAdd(&g_bnsq[c], q);
}

template<int COUT>
__global__ void k_bn(float* __restrict__ out, const float* __restrict__ gam,
                     const float* __restrict__ bet, int total, float invN) {
    int idx = blockIdx.x * blockDim.x + threadIdx.x;
    if (idx >= total) return;
    int c = idx & (COUT - 1);
    float m = g_bnsum[c] * invN;
    float v = g_bnsq[c] * invN - m * m;
    float y = (g_agg[idx] - m) * rsqrtf(v + 1e-5f) * gam[c] + bet[c];
    out[idx] = fmaxf(y, 0.f);
}

// ---------------- launch ----------------
extern "C" void kernel_launch(void* const* d_in, const int* in_sizes, int n_in,
                              void* d_out, int out_size) {
    const float* x   = (const float*)d_in[0];
    const void*  ei  = d_in[1];
    const float* ew  = (const float*)d_in[2];
    const float* W0  = (const float*)d_in[3];
    const float* b0  = (const float*)d_in[4];
    const float* ga0 = (const float*)d_in[5];
    const float* be0 = (const float*)d_in[6];
    const float* W1  = (const float*)d_in[7];
    const float* b1  = (const float*)d_in[8];
    const float* ga1 = (const float*)d_in[9];
    const float* be1 = (const float*)d_in[10];
    const float* Wf  = (const float*)d_in[11];
    const float* bf  = (const float*)d_in[12];
    const float* gaf = (const float*)d_in[13];
    const float* bef = (const float*)d_in[14];

    int N = in_sizes[0] / CH;
    int E = in_sizes[2];
    float invN = 1.0f / (float)N;

    float* h_ptr = nullptr;
    cudaGetSymbolAddress((void**)&h_ptr, g_h);

    int nb_n = (N + 255) / 256;
    int nb_e = (E + 255) / 256;

    // ---- preprocessing: degrees, norms, CSR by destination ----
    k_detect<<<1, 1>>>(ei);
    k_init<<<nb_n, 256>>>(N);
    k_deg<<<nb_e, 256>>>(ei, ew, E);
    k_dis<<<nb_n, 256>>>(N);
    k_scan<<<1, 1024>>>(N);
    k_fill<<<nb_e, 256>>>(ei, ew, E);

    int gemm_blocks = (N + 127) / 128;
    int agg_blocks  = (N * 32 + 255) / 256;

    // ---- layer 0: x -> g_h ----
    k_gemm<CH><<<gemm_blocks, 256>>>(x, W0, N);
    k_agg<CH><<<agg_blocks, 256>>>(b0, N);
    k_zerobn<<<1, CH>>>();
    k_bnreduce<CH><<<240, CH>>>(N);
    k_bn<CH><<<(N * CH + 255) / 256, 256>>>(h_ptr, ga0, be0, N * CH, invN);

    // ---- layer 1: g_h -> g_h ----
    k_gemm<CH><<<gemm_blocks, 256>>>(h_ptr, W1, N);
    k_agg<CH><<<agg_blocks, 256>>>(b1, N);
    k_zerobn<<<1, CH>>>();
    k_bnreduce<CH><<<240, CH>>>(N);
    k_bn<CH><<<(N * CH + 255) / 256, 256>>>(h_ptr, ga1, be1, N * CH, invN);

    // ---- layer 2: g_h -> d_out (64 ch) ----
    k_gemm<LOUT><<<gemm_blocks, 256>>>(h_ptr, Wf, N);
    k_agg<LOUT><<<agg_blocks, 256>>>(bf, N);
    k_zerobn<<<1, CH>>>();
    k_bnreduce<LOUT><<<240, LOUT>>>(N);
    k_bn<LOUT><<<(N * LOUT + 255) / 256, 256>>>((float*)d_out, gaf, bef, N * LOUT, invN);
}